// round 1
// baseline (speedup 1.0000x reference)
#include <cuda_runtime.h>

#define HDIM 1024
#define BDIM 64
#define TM   64
#define KC   32
#define NT   128

// Precomputed weight transforms (device globals; no allocation).
__device__ float g_w2T[HDIM * BDIM];   // [h][d] : down_w[d][h] * norm_w[h]
__device__ float g_upwT[BDIM * HDIM];  // [d][n] : up_w[n][d] transposed
__device__ float g_c1[BDIM];           // sum_h down_w[d][h]*norm_w[h]
__device__ float g_c2[BDIM];           // sum_h down_w[d][h]*norm_b[h] + down_b[d]

// Packed 2-wide fp32 FMA (FFMA2): d = {a,a}*b + c elementwise.
__device__ __forceinline__ float2 ffma2(float a, float2 b, float2 c) {
    union U { float2 f; unsigned long long u; };
    U A, B, C;
    A.f.x = a; A.f.y = a;
    B.f = b; C.f = c;
    asm("fma.rn.f32x2 %0, %1, %2, %3;"
        : "=l"(C.u) : "l"(A.u), "l"(B.u), "l"(C.u));
    return C.f;
}

// ---------------- prep kernels (tiny) ----------------

__global__ void prep_transpose(const float* __restrict__ down_w,
                               const float* __restrict__ norm_w,
                               const float* __restrict__ up_w) {
    int idx = blockIdx.x * 256 + threadIdx.x;   // 0..65535
    // down_w [64][1024] -> g_w2T[h][d] (fold norm_w)
    int d = idx >> 10, h = idx & 1023;
    g_w2T[h * BDIM + d] = down_w[idx] * norm_w[h];
    // up_w [1024][64] -> g_upwT[d][n]
    int n = idx >> 6, dd = idx & 63;
    g_upwT[dd * HDIM + n] = up_w[idx];
}

__global__ void prep_c(const float* __restrict__ down_w,
                       const float* __restrict__ norm_w,
                       const float* __restrict__ norm_b,
                       const float* __restrict__ down_b) {
    int d = blockIdx.x;                         // 64 blocks
    __shared__ float r1[256], r2[256];
    float s1 = 0.f, s2 = 0.f;
    for (int h = threadIdx.x; h < HDIM; h += 256) {
        float dw = down_w[d * HDIM + h];
        s1 += dw * norm_w[h];
        s2 += dw * norm_b[h];
    }
    r1[threadIdx.x] = s1; r2[threadIdx.x] = s2;
    __syncthreads();
    for (int s = 128; s > 0; s >>= 1) {
        if (threadIdx.x < s) {
            r1[threadIdx.x] += r1[threadIdx.x + s];
            r2[threadIdx.x] += r2[threadIdx.x + s];
        }
        __syncthreads();
    }
    if (threadIdx.x == 0) {
        g_c1[d] = r1[0];
        g_c2[d] = r2[0] + down_b[d];
    }
}

// ---------------- fused main kernel ----------------
// CTA = 128 threads, 64 rows. Warp tile 32r x 32n; lane = (lr 0..7, ln 0..3);
// thread computes 4 rows x 8 cols (4 f32x2 pairs).

__global__ __launch_bounds__(NT) void adapter_kernel(
    const float* __restrict__ x,
    const float* __restrict__ up_b,
    float* __restrict__ out)
{
    __shared__ float hT[BDIM][TM + 1];            // gelu(h) transposed [d][r]
    __shared__ float smu[TM], srs[TM];
    __shared__ float sc1[BDIM], sc2[BDIM];
    __shared__ float sub[HDIM];
    __shared__ union Ov {
        struct { float xsc[TM][KC + 1]; float2 ws2[KC][BDIM / 2]; } dn;
        struct { float2 uw2[BDIM][32]; } up;      // 64-n chunk of up weights
    } ov;

    const int tid  = threadIdx.x;
    const int w    = tid >> 5, lane = tid & 31;
    const int lr   = lane >> 2, ln = lane & 3;
    const int wr   = w >> 1,   wc = w & 1;
    const int r0   = wr * 32 + lr * 4;            // thread row base in tile
    const int pb   = wc * 16 + ln * 4;            // f32x2 pair base (n = 2*pb)
    const size_t rbase = (size_t)blockIdx.x * TM;

    // ---- phase 0: stage constants + per-row stats ----
    for (int i = tid; i < BDIM; i += NT) { sc1[i] = g_c1[i]; sc2[i] = g_c2[i]; }
    for (int i = tid; i < HDIM; i += NT) sub[i] = up_b[i];

    for (int rl = w * 16; rl < w * 16 + 16; rl++) {
        const float4* xr = reinterpret_cast<const float4*>(x + (rbase + rl) * HDIM);
        float s = 0.f, q = 0.f;
        #pragma unroll
        for (int i = lane; i < HDIM / 4; i += 32) {
            float4 v = xr[i];
            s += (v.x + v.y) + (v.z + v.w);
            q += v.x * v.x + v.y * v.y + v.z * v.z + v.w * v.w;
        }
        #pragma unroll
        for (int o = 16; o; o >>= 1) {
            s += __shfl_xor_sync(0xffffffffu, s, o);
            q += __shfl_xor_sync(0xffffffffu, q, o);
        }
        if (lane == 0) {
            float mu  = s * (1.0f / HDIM);
            float var = fmaxf(q * (1.0f / HDIM) - mu * mu, 0.0f);
            smu[rl] = mu;
            srs[rl] = rsqrtf(var + 1e-5f);
        }
    }
    __syncthreads();

    // ---- phase 1: down GEMM on raw x (LN folded into epilogue) ----
    float2 acc[4][4];
    #pragma unroll
    for (int i = 0; i < 4; i++)
        #pragma unroll
        for (int j = 0; j < 4; j++) acc[i][j] = make_float2(0.f, 0.f);

    for (int k0 = 0; k0 < HDIM; k0 += KC) {
        for (int i = tid; i < TM * KC; i += NT) {
            int r = i >> 5, kk = i & (KC - 1);
            ov.dn.xsc[r][kk] = x[(rbase + r) * HDIM + k0 + kk];
        }
        for (int i = tid; i < KC * (BDIM / 2); i += NT) {
            int kk = i >> 5, p = i & 31;
            ov.dn.ws2[kk][p] =
                reinterpret_cast<const float2*>(g_w2T + (size_t)(k0 + kk) * BDIM)[p];
        }
        __syncthreads();
        #pragma unroll 4
        for (int kk = 0; kk < KC; kk++) {
            float2 wv[4];
            #pragma unroll
            for (int j = 0; j < 4; j++) wv[j] = ov.dn.ws2[kk][pb + j];
            #pragma unroll
            for (int i = 0; i < 4; i++) {
                float xv = ov.dn.xsc[r0 + i][kk];
                #pragma unroll
                for (int j = 0; j < 4; j++)
                    acc[i][j] = ffma2(xv, wv[j], acc[i][j]);
            }
        }
        __syncthreads();
    }

    // ---- down epilogue: LN fixup + bias + exact GELU -> hT ----
    #pragma unroll
    for (int i = 0; i < 4; i++) {
        int r = r0 + i;
        float mu = smu[r], rv = srs[r];
        #pragma unroll
        for (int j = 0; j < 4; j++) {
            int n0 = 2 * (pb + j);
            float v0 = rv * (acc[i][j].x - mu * sc1[n0]) + sc2[n0];
            float v1 = rv * (acc[i][j].y - mu * sc1[n0 + 1]) + sc2[n0 + 1];
            hT[n0][r]     = 0.5f * v0 * (1.0f + erff(v0 * 0.70710678118f));
            hT[n0 + 1][r] = 0.5f * v1 * (1.0f + erff(v1 * 0.70710678118f));
        }
    }
    __syncthreads();

    // ---- phase 2: up GEMM (K=64) + bias + residual, 16 chunks of 64 n ----
    for (int nc = 0; nc < HDIM; nc += 64) {
        for (int i = tid; i < BDIM * 32; i += NT) {
            int kk = i >> 5, p = i & 31;
            ov.up.uw2[kk][p] =
                reinterpret_cast<const float2*>(g_upwT + (size_t)kk * HDIM + nc)[p];
        }
        __syncthreads();

        float2 ua[4][4];
        #pragma unroll
        for (int i = 0; i < 4; i++)
            #pragma unroll
            for (int j = 0; j < 4; j++) ua[i][j] = make_float2(0.f, 0.f);

        #pragma unroll 4
        for (int kk = 0; kk < BDIM; kk++) {
            float2 wv[4];
            #pragma unroll
            for (int j = 0; j < 4; j++) wv[j] = ov.up.uw2[kk][pb + j];
            #pragma unroll
            for (int i = 0; i < 4; i++) {
                float hv = hT[kk][r0 + i];
                #pragma unroll
                for (int j = 0; j < 4; j++)
                    ua[i][j] = ffma2(hv, wv[j], ua[i][j]);
            }
        }

        #pragma unroll
        for (int i = 0; i < 4; i++) {
            size_t off = (rbase + r0 + i) * HDIM + nc + 2 * pb;
            int nb = nc + 2 * pb;
            float4 xa = *reinterpret_cast<const float4*>(x + off);
            float4 xb = *reinterpret_cast<const float4*>(x + off + 4);
            float4 oa, ob;
            oa.x = xa.x + ua[i][0].x + sub[nb + 0];
            oa.y = xa.y + ua[i][0].y + sub[nb + 1];
            oa.z = xa.z + ua[i][1].x + sub[nb + 2];
            oa.w = xa.w + ua[i][1].y + sub[nb + 3];
            ob.x = xb.x + ua[i][2].x + sub[nb + 4];
            ob.y = xb.y + ua[i][2].y + sub[nb + 5];
            ob.z = xb.z + ua[i][3].x + sub[nb + 6];
            ob.w = xb.w + ua[i][3].y + sub[nb + 7];
            *reinterpret_cast<float4*>(out + off)     = oa;
            *reinterpret_cast<float4*>(out + off + 4) = ob;
        }
        __syncthreads();
    }
}

// ---------------- launch ----------------

extern "C" void kernel_launch(void* const* d_in, const int* in_sizes, int n_in,
                              void* d_out, int out_size) {
    const float* x      = (const float*)d_in[0];
    const float* norm_w = (const float*)d_in[1];
    const float* norm_b = (const float*)d_in[2];
    const float* down_w = (const float*)d_in[3];
    const float* down_b = (const float*)d_in[4];
    const float* up_w   = (const float*)d_in[5];
    const float* up_b   = (const float*)d_in[6];
    float* out = (float*)d_out;

    int rows = in_sizes[0] / HDIM;

    prep_transpose<<<(HDIM * BDIM) / 256, 256>>>(down_w, norm_w, up_w);
    prep_c<<<BDIM, 256>>>(down_w, norm_w, norm_b, down_b);
    adapter_kernel<<<rows / TM, NT>>>(x, up_b, out);
}

// round 5
// speedup vs baseline: 1.9180x; 1.9180x over previous
#include <cuda_runtime.h>
#include <cstdint>

#define HDIM 1024
#define BDIM 64
#define TM   128
#define NT   256
#define NCHUNK 16

// ---- shared memory layout (float offsets) ----
#define O_SUB 0
#define O_C1  1024
#define O_C2  1088
#define O_MU  1152
#define O_RS  1280
#define O_XA0 1408
#define O_XA1 (O_XA0 + 8192)
#define O_W0  (O_XA1 + 8192)
#define O_W1  (O_W0 + 4096)
#define SMEM_FLOATS (O_W1 + 4096)        // 25984 floats = 103,936 B
#define O_H   O_XA0                      // h aliases x buffer 0 after phase A

__device__ float g_w2[BDIM * HDIM];      // tf32(down_w * norm_w), [d][h]
__device__ float g_c1[BDIM];
__device__ float g_c2[BDIM];

// ---------------- helpers ----------------
__device__ __forceinline__ uint32_t f2tf32(float f) {
    uint32_t u; asm("cvt.rna.tf32.f32 %0, %1;" : "=r"(u) : "f"(f)); return u;
}
__device__ __forceinline__ uint4 cvt4(float4 v) {
    uint4 u;
    u.x = f2tf32(v.x); u.y = f2tf32(v.y); u.z = f2tf32(v.z); u.w = f2tf32(v.w);
    return u;
}
__device__ __forceinline__ void mma8(float* c, const uint32_t* a,
                                     uint32_t b0, uint32_t b1) {
    asm volatile(
        "mma.sync.aligned.m16n8k8.row.col.f32.tf32.tf32.f32 "
        "{%0,%1,%2,%3}, {%4,%5,%6,%7}, {%8,%9}, {%0,%1,%2,%3};"
        : "+f"(c[0]), "+f"(c[1]), "+f"(c[2]), "+f"(c[3])
        : "r"(a[0]), "r"(a[1]), "r"(a[2]), "r"(a[3]), "r"(b0), "r"(b1));
}
// XOR-swizzled word offset inside a [rows][64] tile (pitch 64, no padding)
__device__ __forceinline__ int swa(int r, int col) {
    return (r << 6) + ((((col >> 2) ^ (r & 7)) << 2) | (col & 3));
}
__device__ __forceinline__ int sw4(int r, int slot) {   // float4 granularity
    return (r << 6) + ((slot ^ (r & 7)) << 2);
}
__device__ __forceinline__ float gelu(float v) {
    return 0.5f * v * (1.0f + erff(v * 0.70710678118654752f));
}

// ---------------- prep: w2 = tf32(down_w*norm_w), c1/c2 ----------------
__global__ void prep_kernel(const float* __restrict__ down_w,
                            const float* __restrict__ norm_w,
                            const float* __restrict__ norm_b,
                            const float* __restrict__ down_b) {
    __shared__ float r1[256], r2[256];
    int d = blockIdx.x;
    float s1 = 0.f, s2 = 0.f;
    for (int h = threadIdx.x; h < HDIM; h += 256) {
        float dw = down_w[d * HDIM + h];
        float w2 = __uint_as_float(f2tf32(dw * norm_w[h]));
        g_w2[d * HDIM + h] = w2;
        s1 += w2;
        s2 += dw * norm_b[h];
    }
    r1[threadIdx.x] = s1; r2[threadIdx.x] = s2;
    __syncthreads();
    for (int st = 128; st > 0; st >>= 1) {
        if (threadIdx.x < st) {
            r1[threadIdx.x] += r1[threadIdx.x + st];
            r2[threadIdx.x] += r2[threadIdx.x + st];
        }
        __syncthreads();
    }
    if (threadIdx.x == 0) { g_c1[d] = r1[0]; g_c2[d] = r2[0] + down_b[d]; }
}

// ---------------- fused main kernel ----------------
__global__ void __launch_bounds__(NT, 2)
adapter_main(const float* __restrict__ x,
             const float* __restrict__ up_b,
             const float* __restrict__ up_w,
             float* __restrict__ out) {
    extern __shared__ float sm[];
    const int tid  = threadIdx.x;
    const int lane = tid & 31, w = tid >> 5;
    const int g    = lane >> 2, t4 = lane & 3;
    const int g4   = tid >> 4, s = tid & 15;
    const size_t rbase = (size_t)blockIdx.x * TM;

    for (int i = tid; i < HDIM; i += NT) sm[O_SUB + i] = up_b[i];
    if (tid < BDIM) { sm[O_C1 + tid] = g_c1[tid]; sm[O_C2 + tid] = g_c2[tid]; }

    float ssum[8], ssq[8];
    #pragma unroll
    for (int u = 0; u < 8; u++) { ssum[u] = 0.f; ssq[u] = 0.f; }

    // ---- prologue: stage chunk 0 ----
    {
        float4 vx[8], vw[4];
        #pragma unroll
        for (int u = 0; u < 8; u++)
            vx[u] = *(const float4*)(x + (rbase + u * 16 + g4) * HDIM + s * 4);
        #pragma unroll
        for (int u = 0; u < 4; u++)
            vw[u] = *(const float4*)(g_w2 + (u * 16 + g4) * HDIM + s * 4);
        #pragma unroll
        for (int u = 0; u < 8; u++) {
            ssum[u] += (vx[u].x + vx[u].y) + (vx[u].z + vx[u].w);
            ssq[u]  += vx[u].x * vx[u].x + vx[u].y * vx[u].y
                     + vx[u].z * vx[u].z + vx[u].w * vx[u].w;
            *(uint4*)(sm + O_XA0 + sw4(u * 16 + g4, s)) = cvt4(vx[u]);
        }
        #pragma unroll
        for (int u = 0; u < 4; u++)
            *(uint4*)(sm + O_W0 + sw4(u * 16 + g4, s)) = cvt4(vw[u]);
    }
    __syncthreads();

    // ---- phase A: down GEMM (M=128,N=64,K=1024), K double-buffered ----
    float acc[8][4];
    #pragma unroll
    for (int nt = 0; nt < 8; nt++)
        #pragma unroll
        for (int j = 0; j < 4; j++) acc[nt][j] = 0.f;

    for (int c = 0; c < NCHUNK; c++) {
        float4 vx[8], vw[4];
        if (c + 1 < NCHUNK) {
            #pragma unroll
            for (int u = 0; u < 8; u++)
                vx[u] = *(const float4*)(x + (rbase + u * 16 + g4) * HDIM
                                           + (c + 1) * 64 + s * 4);
            #pragma unroll
            for (int u = 0; u < 4; u++)
                vw[u] = *(const float4*)(g_w2 + (u * 16 + g4) * HDIM
                                              + (c + 1) * 64 + s * 4);
        }
        const float* XA = sm + ((c & 1) ? O_XA1 : O_XA0);
        const float* W  = sm + ((c & 1) ? O_W1 : O_W0);
        #pragma unroll
        for (int kt = 0; kt < 8; kt++) {
            uint32_t a[4];
            a[0] = __float_as_uint(XA[swa(w * 16 + g,     kt * 8 + t4)]);
            a[1] = __float_as_uint(XA[swa(w * 16 + g + 8, kt * 8 + t4)]);
            a[2] = __float_as_uint(XA[swa(w * 16 + g,     kt * 8 + t4 + 4)]);
            a[3] = __float_as_uint(XA[swa(w * 16 + g + 8, kt * 8 + t4 + 4)]);
            #pragma unroll
            for (int nt = 0; nt < 8; nt++) {
                uint32_t b0 = __float_as_uint(W[swa(nt * 8 + g, kt * 8 + t4)]);
                uint32_t b1 = __float_as_uint(W[swa(nt * 8 + g, kt * 8 + t4 + 4)]);
                mma8(acc[nt], a, b0, b1);
            }
        }
        if (c + 1 < NCHUNK) {
            float* XN = sm + ((c & 1) ? O_XA0 : O_XA1);
            float* WN = sm + ((c & 1) ? O_W0 : O_W1);
            #pragma unroll
            for (int u = 0; u < 8; u++) {
                ssum[u] += (vx[u].x + vx[u].y) + (vx[u].z + vx[u].w);
                ssq[u]  += vx[u].x * vx[u].x + vx[u].y * vx[u].y
                         + vx[u].z * vx[u].z + vx[u].w * vx[u].w;
                *(uint4*)(XN + sw4(u * 16 + g4, s)) = cvt4(vx[u]);
            }
            #pragma unroll
            for (int u = 0; u < 4; u++)
                *(uint4*)(WN + sw4(u * 16 + g4, s)) = cvt4(vw[u]);
        }
        __syncthreads();
    }

    // ---- stats reduction across the 16 column-slice lanes ----
    #pragma unroll
    for (int u = 0; u < 8; u++) {
        float sv = ssum[u], qv = ssq[u];
        #pragma unroll
        for (int o = 1; o < 16; o <<= 1) {
            sv += __shfl_xor_sync(0xffffffffu, sv, o);
            qv += __shfl_xor_sync(0xffffffffu, qv, o);
        }
        ssum[u] = sv; ssq[u] = qv;
    }
    if (s == 0) {
        #pragma unroll
        for (int u = 0; u < 8; u++) {
            float mu  = ssum[u] * (1.0f / HDIM);
            float var = fmaxf(ssq[u] * (1.0f / HDIM) - mu * mu, 0.0f);
            sm[O_MU + u * 16 + g4] = mu;
            sm[O_RS + u * 16 + g4] = rsqrtf(var + 1e-5f);
        }
    }
    __syncthreads();

    // ---- epilogue A: LN fixup + bias + exact GELU -> tf32 h in smem ----
    const int rA = w * 16 + g, rB = rA + 8;
    {
        float muA = sm[O_MU + rA], rsA = sm[O_RS + rA];
        float muB = sm[O_MU + rB], rsB = sm[O_RS + rB];
        float* H = sm + O_H;
        #pragma unroll
        for (int nt = 0; nt < 8; nt++) {
            int n0 = nt * 8 + 2 * t4;
            float c1a = sm[O_C1 + n0], c1b = sm[O_C1 + n0 + 1];
            float c2a = sm[O_C2 + n0], c2b = sm[O_C2 + n0 + 1];
            float v0 = gelu(rsA * (acc[nt][0] - muA * c1a) + c2a);
            float v1 = gelu(rsA * (acc[nt][1] - muA * c1b) + c2b);
            float v2 = gelu(rsB * (acc[nt][2] - muB * c1a) + c2a);
            float v3 = gelu(rsB * (acc[nt][3] - muB * c1b) + c2b);
            *(uint2*)(H + swa(rA, n0)) = make_uint2(f2tf32(v0), f2tf32(v1));
            *(uint2*)(H + swa(rB, n0)) = make_uint2(f2tf32(v2), f2tf32(v3));
        }
    }
    __syncthreads();

    // ---- phase B: up GEMM (K=64), 16 n-chunks of 64, fused residual ----
    {
        float4 vw[4];
        #pragma unroll
        for (int u = 0; u < 4; u++)
            vw[u] = *(const float4*)(up_w + (size_t)(u * 16 + g4) * BDIM + s * 4);
        #pragma unroll
        for (int u = 0; u < 4; u++)
            *(uint4*)(sm + O_W0 + sw4(u * 16 + g4, s)) = cvt4(vw[u]);
    }
    __syncthreads();

    for (int nc = 0; nc < 16; nc++) {
        float4 vw[4];
        if (nc + 1 < 16) {
            #pragma unroll
            for (int u = 0; u < 4; u++)
                vw[u] = *(const float4*)(up_w
                            + (size_t)((nc + 1) * 64 + u * 16 + g4) * BDIM + s * 4);
        }
        // residual prefetch for this chunk
        float2 rxA[8], rxB[8];
        #pragma unroll
        for (int nt = 0; nt < 8; nt++) {
            int col = nc * 64 + nt * 8 + 2 * t4;
            rxA[nt] = *(const float2*)(x + (rbase + rA) * HDIM + col);
            rxB[nt] = *(const float2*)(x + (rbase + rB) * HDIM + col);
        }

        float ua[8][4];
        #pragma unroll
        for (int nt = 0; nt < 8; nt++)
            #pragma unroll
            for (int j = 0; j < 4; j++) ua[nt][j] = 0.f;

        const float* H = sm + O_H;
        const float* W = sm + ((nc & 1) ? O_W1 : O_W0);
        #pragma unroll
        for (int kt = 0; kt < 8; kt++) {
            uint32_t a[4];
            a[0] = __float_as_uint(H[swa(rA, kt * 8 + t4)]);
            a[1] = __float_as_uint(H[swa(rB, kt * 8 + t4)]);
            a[2] = __float_as_uint(H[swa(rA, kt * 8 + t4 + 4)]);
            a[3] = __float_as_uint(H[swa(rB, kt * 8 + t4 + 4)]);
            #pragma unroll
            for (int nt = 0; nt < 8; nt++) {
                uint32_t b0 = __float_as_uint(W[swa(nt * 8 + g, kt * 8 + t4)]);
                uint32_t b1 = __float_as_uint(W[swa(nt * 8 + g, kt * 8 + t4 + 4)]);
                mma8(ua[nt], a, b0, b1);
            }
        }
        if (nc + 1 < 16) {
            float* WN = sm + ((nc & 1) ? O_W0 : O_W1);
            #pragma unroll
            for (int u = 0; u < 4; u++)
                *(uint4*)(WN + sw4(u * 16 + g4, s)) = cvt4(vw[u]);
        }
        // epilogue: residual + up_b + store
        #pragma unroll
        for (int nt = 0; nt < 8; nt++) {
            int col = nc * 64 + nt * 8 + 2 * t4;
            float b0 = sm[O_SUB + col], b1 = sm[O_SUB + col + 1];
            float2 oA = make_float2(rxA[nt].x + ua[nt][0] + b0,
                                    rxA[nt].y + ua[nt][1] + b1);
            float2 oB = make_float2(rxB[nt].x + ua[nt][2] + b0,
                                    rxB[nt].y + ua[nt][3] + b1);
            *(float2*)(out + (rbase + rA) * HDIM + col) = oA;
            *(float2*)(out + (rbase + rB) * HDIM + col) = oB;
        }
        __syncthreads();
    }
}

// ---------------- launch ----------------
extern "C" void kernel_launch(void* const* d_in, const int* in_sizes, int n_in,
                              void* d_out, int out_size) {
    const float* x      = (const float*)d_in[0];
    const float* norm_w = (const float*)d_in[1];
    const float* norm_b = (const float*)d_in[2];
    const float* down_w = (const float*)d_in[3];
    const float* down_b = (const float*)d_in[4];
    const float* up_w   = (const float*)d_in[5];
    const float* up_b   = (const float*)d_in[6];
    float* out = (float*)d_out;

    int rows = in_sizes[0] / HDIM;

    cudaFuncSetAttribute(adapter_main,
                         cudaFuncAttributeMaxDynamicSharedMemorySize,
                         SMEM_FLOATS * 4);

    prep_kernel<<<BDIM, 256>>>(down_w, norm_w, norm_b, down_b);
    adapter_main<<<rows / TM, NT, SMEM_FLOATS * 4>>>(x, up_b, up_w, out);
}

// round 8
// speedup vs baseline: 2.6174x; 1.3646x over previous
#include <cuda_runtime.h>
#include <cuda_fp16.h>
#include <cstdint>

#define HDIM 1024
#define BDIM 64
#define TM   128
#define NT   256

// ---- dynamic smem byte offsets ----
#define O_SUB 0              // up_b, 4KB fp32
#define O_C1  4096           // 256B
#define O_C2  4352
#define O_MU  4608           // 512B fp32
#define O_RS  5120
#define O_XA0 6144           // 16KB fp16 tile image [128r][64k]
#define O_XA1 22528
#define O_W0  38912          // 8KB fp16 tile image [64k][64n]
#define O_W1  47104
#define SMEM_BYTES 55296
#define O_H   O_XA0          // h image aliases XA0 after phase A

__device__ __half g_w2h[16 * 4096];   // swizzled [kc][k][unit] images, B=[k][d]
__device__ __half g_uph[16 * 4096];   // swizzled [nc][k][unit] images, B=[d][n]
__device__ float  g_c1[BDIM];
__device__ float  g_c2[BDIM];

// ---------------- helpers ----------------
__device__ __forceinline__ uint32_t smem_u32(const void* p) {
    uint32_t a;
    asm("{ .reg .u64 t; cvta.to.shared.u64 t, %1; cvt.u32.u64 %0, t; }"
        : "=r"(a) : "l"(p));
    return a;
}
__device__ __forceinline__ uint32_t pk2(float a, float b) {
    __half2 h = __floats2half2_rn(a, b);
    return *reinterpret_cast<uint32_t*>(&h);
}
__device__ __forceinline__ void ldm4(uint32_t* r, uint32_t addr) {
    asm volatile("ldmatrix.sync.aligned.m8n8.x4.shared.b16 {%0,%1,%2,%3}, [%4];"
                 : "=r"(r[0]), "=r"(r[1]), "=r"(r[2]), "=r"(r[3]) : "r"(addr));
}
__device__ __forceinline__ void ldm4t(uint32_t* r, uint32_t addr) {
    asm volatile("ldmatrix.sync.aligned.m8n8.x4.trans.shared.b16 {%0,%1,%2,%3}, [%4];"
                 : "=r"(r[0]), "=r"(r[1]), "=r"(r[2]), "=r"(r[3]) : "r"(addr));
}
__device__ __forceinline__ void mma16(float* c, const uint32_t* a,
                                      uint32_t b0, uint32_t b1) {
    asm volatile(
        "mma.sync.aligned.m16n8k16.row.col.f32.f16.f16.f32 "
        "{%0,%1,%2,%3}, {%4,%5,%6,%7}, {%8,%9}, {%0,%1,%2,%3};"
        : "+f"(c[0]), "+f"(c[1]), "+f"(c[2]), "+f"(c[3])
        : "r"(a[0]), "r"(a[1]), "r"(a[2]), "r"(a[3]), "r"(b0), "r"(b1));
}
__device__ __forceinline__ float gelu(float v) {
    return 0.5f * v * (1.0f + erff(v * 0.70710678118654752f));
}

// ---------------- prep: build swizzled fp16 weight images ----------------
__global__ void prep_images(const float* __restrict__ down_w,
                            const float* __restrict__ norm_w,
                            const float* __restrict__ up_w) {
    int idx = blockIdx.x * 256 + threadIdx.x;       // 0..65535
    int cc = idx >> 12, rem = idx & 4095;
    int k = rem >> 6, c = (rem >> 3) & 7, i = rem & 7;
    int log_u = c ^ (k & 7);                        // logical n-unit at stored slot c
    // down image: B[k][n=d] = down_w[d][h]*norm_w[h], h = cc*64+k
    int d = log_u * 8 + i;
    int h = cc * 64 + k;
    g_w2h[idx] = __float2half_rn(down_w[d * HDIM + h] * norm_w[h]);
    // up image: B[k=d][n] = up_w[n][d], n = cc*64 + log_u*8 + i
    int n = cc * 64 + log_u * 8 + i;
    g_uph[idx] = __float2half_rn(up_w[n * BDIM + k]);
}

__global__ void prep_c(const float* __restrict__ down_w,
                       const float* __restrict__ norm_w,
                       const float* __restrict__ norm_b,
                       const float* __restrict__ down_b) {
    __shared__ float r1[256], r2[256];
    int d = blockIdx.x;
    float s1 = 0.f, s2 = 0.f;
    for (int h = threadIdx.x; h < HDIM; h += 256) {
        float dw = down_w[d * HDIM + h];
        // c1 must match the fp16-rounded weight actually used in the GEMM
        float w2 = __half2float(__float2half_rn(dw * norm_w[h]));
        s1 += w2;
        s2 += dw * norm_b[h];
    }
    r1[threadIdx.x] = s1; r2[threadIdx.x] = s2;
    __syncthreads();
    for (int st = 128; st > 0; st >>= 1) {
        if (threadIdx.x < st) {
            r1[threadIdx.x] += r1[threadIdx.x + st];
            r2[threadIdx.x] += r2[threadIdx.x + st];
        }
        __syncthreads();
    }
    if (threadIdx.x == 0) { g_c1[d] = r1[0]; g_c2[d] = r2[0] + down_b[d]; }
}

// ---------------- fused main kernel ----------------
__global__ void __launch_bounds__(NT, 2)
adapter_main(const float* __restrict__ x,
             const float* __restrict__ up_b,
             float* __restrict__ out) {
    extern __shared__ char smc[];
    const uint32_t sb = smem_u32(smc);
    float* SUB = (float*)(smc + O_SUB);
    float* C1  = (float*)(smc + O_C1);
    float* C2  = (float*)(smc + O_C2);
    float* MU  = (float*)(smc + O_MU);
    float* RS  = (float*)(smc + O_RS);

    const int tid  = threadIdx.x;
    const int lane = tid & 31, w = tid >> 5;
    const int g    = lane >> 2, t4 = lane & 3;
    const int w_m  = w >> 1,   w_n = w & 1;
    const size_t rbase = (size_t)blockIdx.x * TM;

    // loader role
    const int r_l = tid >> 1, hf = tid & 1;
    // ldmatrix address components
    const int laneq = lane & 7;
    const int half8 = (lane >> 3) & 1;
    const int hi16  = lane >> 4;
    int ofsA[2], colA[4], ofsB[2];
    #pragma unroll
    for (int mt = 0; mt < 2; mt++)
        ofsA[mt] = (w_m * 32 + mt * 16 + half8 * 8 + laneq) * 128;
    #pragma unroll
    for (int kt = 0; kt < 4; kt++)
        colA[kt] = ((kt * 2 + hi16) ^ laneq) * 16;
    {
        int kb0 = half8 * 8 + laneq;
        #pragma unroll
        for (int p = 0; p < 2; p++)
            ofsB[p] = kb0 * 128 + ((w_n * 4 + p * 2 + hi16) ^ laneq) * 16;
    }
    // x STS offsets (4 x uint4 per thread)
    int stsOfs[4];
    #pragma unroll
    for (int j = 0; j < 4; j++)
        stsOfs[j] = r_l * 128 + (((hf * 4 + j) ^ (r_l & 7)) * 16);

    for (int i = tid; i < HDIM; i += NT) SUB[i] = up_b[i];
    if (tid < BDIM) { C1[tid] = g_c1[tid]; C2[tid] = g_c2[tid]; }

    float s_acc = 0.f, q_acc = 0.f;

    // ---- prologue: stage chunk 0 (x + down-w image) ----
    {
        const float4* xr = (const float4*)(x + (rbase + r_l) * HDIM + hf * 32);
        float4 px[8];
        #pragma unroll
        for (int j = 0; j < 8; j++) px[j] = xr[j];
        #pragma unroll
        for (int j = 0; j < 8; j++) {
            s_acc += (px[j].x + px[j].y) + (px[j].z + px[j].w);
            q_acc += px[j].x * px[j].x + px[j].y * px[j].y
                   + px[j].z * px[j].z + px[j].w * px[j].w;
        }
        #pragma unroll
        for (int j = 0; j < 4; j++) {
            uint4 u = make_uint4(pk2(px[2*j].x, px[2*j].y), pk2(px[2*j].z, px[2*j].w),
                                 pk2(px[2*j+1].x, px[2*j+1].y), pk2(px[2*j+1].z, px[2*j+1].w));
            *(uint4*)(smc + O_XA0 + stsOfs[j]) = u;
        }
        const uint4* wsrc = (const uint4*)g_w2h;
        *(uint4*)(smc + O_W0 + tid * 32)      = wsrc[tid * 2];
        *(uint4*)(smc + O_W0 + tid * 32 + 16) = wsrc[tid * 2 + 1];
    }
    __syncthreads();

    // ---- phase A: down GEMM, K=1024 in 16 chunks of 64 ----
    float acc[2][4][4];
    #pragma unroll
    for (int mt = 0; mt < 2; mt++)
        #pragma unroll
        for (int nt = 0; nt < 4; nt++)
            #pragma unroll
            for (int j = 0; j < 4; j++) acc[mt][nt][j] = 0.f;

    for (int c = 0; c < 16; c++) {
        float4 px[8]; uint4 pw0, pw1;
        if (c + 1 < 16) {
            const float4* xr = (const float4*)(x + (rbase + r_l) * HDIM
                                               + (c + 1) * 64 + hf * 32);
            #pragma unroll
            for (int j = 0; j < 8; j++) px[j] = xr[j];
            // one chunk image = 64k x 64n fp16 = 8192 B = 512 uint4
            const uint4* wsrc = (const uint4*)g_w2h + (c + 1) * 512;
            pw0 = wsrc[tid * 2]; pw1 = wsrc[tid * 2 + 1];
        }
        const uint32_t xaB = sb + ((c & 1) ? O_XA1 : O_XA0);
        const uint32_t wB  = sb + ((c & 1) ? O_W1  : O_W0);
        #pragma unroll
        for (int kt = 0; kt < 4; kt++) {
            uint32_t a[2][4], b[2][4];
            ldm4 (a[0], xaB + ofsA[0] + colA[kt]);
            ldm4 (a[1], xaB + ofsA[1] + colA[kt]);
            ldm4t(b[0], wB + kt * 2048 + ofsB[0]);
            ldm4t(b[1], wB + kt * 2048 + ofsB[1]);
            #pragma unroll
            for (int mt = 0; mt < 2; mt++) {
                mma16(acc[mt][0], a[mt], b[0][0], b[0][1]);
                mma16(acc[mt][1], a[mt], b[0][2], b[0][3]);
                mma16(acc[mt][2], a[mt], b[1][0], b[1][1]);
                mma16(acc[mt][3], a[mt], b[1][2], b[1][3]);
            }
        }
        if (c + 1 < 16) {
            const int xaN = (c & 1) ? O_XA0 : O_XA1;
            const int wN  = (c & 1) ? O_W0  : O_W1;
            #pragma unroll
            for (int j = 0; j < 8; j++) {
                s_acc += (px[j].x + px[j].y) + (px[j].z + px[j].w);
                q_acc += px[j].x * px[j].x + px[j].y * px[j].y
                       + px[j].z * px[j].z + px[j].w * px[j].w;
            }
            #pragma unroll
            for (int j = 0; j < 4; j++) {
                uint4 u = make_uint4(pk2(px[2*j].x, px[2*j].y), pk2(px[2*j].z, px[2*j].w),
                                     pk2(px[2*j+1].x, px[2*j+1].y), pk2(px[2*j+1].z, px[2*j+1].w));
                *(uint4*)(smc + xaN + stsOfs[j]) = u;
            }
            *(uint4*)(smc + wN + tid * 32)      = pw0;
            *(uint4*)(smc + wN + tid * 32 + 16) = pw1;
        }
        __syncthreads();
    }

    // ---- LN stats: combine the two half-row threads ----
    {
        float s2 = __shfl_xor_sync(0xffffffffu, s_acc, 1);
        float q2 = __shfl_xor_sync(0xffffffffu, q_acc, 1);
        s_acc += s2; q_acc += q2;
        if (hf == 0) {
            float mu  = s_acc * (1.0f / HDIM);
            float var = fmaxf(q_acc * (1.0f / HDIM) - mu * mu, 0.0f);
            MU[r_l] = mu;
            RS[r_l] = rsqrtf(var + 1e-5f);
        }
    }
    __syncthreads();

    // ---- epilogue A: LN fixup + bias + exact GELU -> fp16 h image ----
    #pragma unroll
    for (int mt = 0; mt < 2; mt++) {
        int rA = w_m * 32 + mt * 16 + g, rB = rA + 8;
        float mu1 = MU[rA], rs1 = RS[rA], mu2 = MU[rB], rs2 = RS[rB];
        #pragma unroll
        for (int nt = 0; nt < 4; nt++) {
            int n = w_n * 32 + nt * 8 + 2 * t4;
            float c1a = C1[n], c1b = C1[n + 1];
            float c2a = C2[n], c2b = C2[n + 1];
            float g0 = gelu(rs1 * (acc[mt][nt][0] - mu1 * c1a) + c2a);
            float g1 = gelu(rs1 * (acc[mt][nt][1] - mu1 * c1b) + c2b);
            float g2 = gelu(rs2 * (acc[mt][nt][2] - mu2 * c1a) + c2a);
            float g3 = gelu(rs2 * (acc[mt][nt][3] - mu2 * c1b) + c2b);
            int u = (w_n * 4 + nt);
            *(uint32_t*)(smc + O_H + rA * 128 + ((u ^ g) * 16) + t4 * 4) = pk2(g0, g1);
            *(uint32_t*)(smc + O_H + rB * 128 + ((u ^ g) * 16) + t4 * 4) = pk2(g2, g3);
        }
    }
    __syncthreads();

    // ---- phase B prologue: stage up-w chunk 0, load h fragments ----
    {
        const uint4* usrc = (const uint4*)g_uph;
        *(uint4*)(smc + O_W0 + tid * 32)      = usrc[tid * 2];
        *(uint4*)(smc + O_W0 + tid * 32 + 16) = usrc[tid * 2 + 1];
    }
    __syncthreads();

    uint32_t ha[4][2][4];
    #pragma unroll
    for (int kt = 0; kt < 4; kt++)
        #pragma unroll
        for (int mt = 0; mt < 2; mt++)
            ldm4(ha[kt][mt], sb + O_H + ofsA[mt] + colA[kt]);

    // ---- phase B: up GEMM (K=64), 16 n-chunks of 64, fused residual ----
    for (int nc = 0; nc < 16; nc++) {
        uint4 pu0, pu1;
        if (nc + 1 < 16) {
            // one chunk image = 8192 B = 512 uint4
            const uint4* usrc = (const uint4*)g_uph + (nc + 1) * 512;
            pu0 = usrc[tid * 2]; pu1 = usrc[tid * 2 + 1];
        }
        const uint32_t uwB = sb + ((nc & 1) ? O_W1 : O_W0);

        float ub[2][4][4];
        #pragma unroll
        for (int mt = 0; mt < 2; mt++)
            #pragma unroll
            for (int nt = 0; nt < 4; nt++)
                #pragma unroll
                for (int j = 0; j < 4; j++) ub[mt][nt][j] = 0.f;

        #pragma unroll
        for (int kt = 0; kt < 4; kt++) {
            uint32_t b[2][4];
            ldm4t(b[0], uwB + kt * 2048 + ofsB[0]);
            ldm4t(b[1], uwB + kt * 2048 + ofsB[1]);
            #pragma unroll
            for (int mt = 0; mt < 2; mt++) {
                mma16(ub[mt][0], ha[kt][mt], b[0][0], b[0][1]);
                mma16(ub[mt][1], ha[kt][mt], b[0][2], b[0][3]);
                mma16(ub[mt][2], ha[kt][mt], b[1][0], b[1][1]);
                mma16(ub[mt][3], ha[kt][mt], b[1][2], b[1][3]);
            }
        }
        if (nc + 1 < 16) {
            const int wN = (nc & 1) ? O_W0 : O_W1;
            *(uint4*)(smc + wN + tid * 32)      = pu0;
            *(uint4*)(smc + wN + tid * 32 + 16) = pu1;
        }

        // epilogue: residual + up_b + store
        #pragma unroll
        for (int mt = 0; mt < 2; mt++) {
            int r1 = w_m * 32 + mt * 16 + g, r2 = r1 + 8;
            const float* xr1 = x + (rbase + r1) * HDIM + nc * 64;
            const float* xr2 = x + (rbase + r2) * HDIM + nc * 64;
            float* or1 = out + (rbase + r1) * HDIM + nc * 64;
            float* or2 = out + (rbase + r2) * HDIM + nc * 64;
            #pragma unroll
            for (int nt = 0; nt < 4; nt++) {
                int nl = w_n * 32 + nt * 8 + 2 * t4;
                float b0 = SUB[nc * 64 + nl], b1 = SUB[nc * 64 + nl + 1];
                float2 xa = *(const float2*)(xr1 + nl);
                float2 xb = *(const float2*)(xr2 + nl);
                float2 oa = make_float2(xa.x + ub[mt][nt][0] + b0,
                                        xa.y + ub[mt][nt][1] + b1);
                float2 ob = make_float2(xb.x + ub[mt][nt][2] + b0,
                                        xb.y + ub[mt][nt][3] + b1);
                *(float2*)(or1 + nl) = oa;
                *(float2*)(or2 + nl) = ob;
            }
        }
        __syncthreads();
    }
}

// ---------------- launch ----------------
extern "C" void kernel_launch(void* const* d_in, const int* in_sizes, int n_in,
                              void* d_out, int out_size) {
    const float* x      = (const float*)d_in[0];
    const float* norm_w = (const float*)d_in[1];
    const float* norm_b = (const float*)d_in[2];
    const float* down_w = (const float*)d_in[3];
    const float* down_b = (const float*)d_in[4];
    const float* up_w   = (const float*)d_in[5];
    const float* up_b   = (const float*)d_in[6];
    float* out = (float*)d_out;

    int rows = in_sizes[0] / HDIM;

    cudaFuncSetAttribute(adapter_main,
                         cudaFuncAttributeMaxDynamicSharedMemorySize, SMEM_BYTES);

    prep_images<<<256, 256>>>(down_w, norm_w, up_w);
    prep_c<<<BDIM, 256>>>(down_w, norm_w, norm_b, down_b);
    adapter_main<<<rows / TM, NT, SMEM_BYTES>>>(x, up_b, out);
}

// round 9
// speedup vs baseline: 2.7588x; 1.0540x over previous
#include <cuda_runtime.h>
#include <cuda_fp16.h>
#include <cstdint>

#define HDIM 1024
#define BDIM 64
#define TM   128
#define NT   256

// ---- dynamic smem byte offsets ----
#define O_SUB 0              // up_b, 4KB fp32
#define O_C1  4096           // 256B
#define O_C2  4352
#define O_MU  4608           // 512B fp32
#define O_RS  5120
#define O_XA0 6144           // 16KB fp16 tile image [128r][64k]
#define O_XA1 22528
#define O_W0  38912          // 8KB fp16 tile image [64k][64n]
#define O_W1  47104
#define SMEM_BYTES 55296
#define O_H   O_XA0          // h image aliases XA0 after phase A

__device__ __half g_w2h[16 * 4096];   // swizzled [kc][k][unit] images, B=[k][d]
__device__ __half g_uph[16 * 4096];   // swizzled [nc][k][unit] images, B=[d][n]
__device__ float  g_c1[BDIM];
__device__ float  g_c2[BDIM];

// ---------------- helpers ----------------
__device__ __forceinline__ uint32_t smem_u32(const void* p) {
    uint32_t a;
    asm("{ .reg .u64 t; cvta.to.shared.u64 t, %1; cvt.u32.u64 %0, t; }"
        : "=r"(a) : "l"(p));
    return a;
}
__device__ __forceinline__ uint32_t pk2(float a, float b) {
    __half2 h = __floats2half2_rn(a, b);
    return *reinterpret_cast<uint32_t*>(&h);
}
__device__ __forceinline__ void cpa16(uint32_t saddr, const void* g) {
    asm volatile("cp.async.cg.shared.global [%0], [%1], 16;"
                 :: "r"(saddr), "l"(g) : "memory");
}
#define CPA_COMMIT() asm volatile("cp.async.commit_group;" ::: "memory")
#define CPA_WAIT0()  asm volatile("cp.async.wait_group 0;" ::: "memory")

__device__ __forceinline__ void ldm4(uint32_t* r, uint32_t addr) {
    asm volatile("ldmatrix.sync.aligned.m8n8.x4.shared.b16 {%0,%1,%2,%3}, [%4];"
                 : "=r"(r[0]), "=r"(r[1]), "=r"(r[2]), "=r"(r[3]) : "r"(addr));
}
__device__ __forceinline__ void ldm4t(uint32_t* r, uint32_t addr) {
    asm volatile("ldmatrix.sync.aligned.m8n8.x4.trans.shared.b16 {%0,%1,%2,%3}, [%4];"
                 : "=r"(r[0]), "=r"(r[1]), "=r"(r[2]), "=r"(r[3]) : "r"(addr));
}
__device__ __forceinline__ void mma16(float* c, const uint32_t* a,
                                      uint32_t b0, uint32_t b1) {
    asm volatile(
        "mma.sync.aligned.m16n8k16.row.col.f32.f16.f16.f32 "
        "{%0,%1,%2,%3}, {%4,%5,%6,%7}, {%8,%9}, {%0,%1,%2,%3};"
        : "+f"(c[0]), "+f"(c[1]), "+f"(c[2]), "+f"(c[3])
        : "r"(a[0]), "r"(a[1]), "r"(a[2]), "r"(a[3]), "r"(b0), "r"(b1));
}
__device__ __forceinline__ float gelu(float v) {
    return 0.5f * v * (1.0f + erff(v * 0.70710678118654752f));
}

// ---------------- merged prep: images + c1/c2, coalesced ----------------
// grid 64, block 256. Block b:
//   part 1: d = b. Read down_w row coalesced (4 floats/thread), fold norm_w,
//           write fp16 image scattered; accumulate c1/c2 and reduce.
//   part 2: flat up_w slice [b*1024, b*1024+1024), coalesced float4 reads.
__global__ void prep_all(const float* __restrict__ down_w,
                         const float* __restrict__ norm_w,
                         const float* __restrict__ norm_b,
                         const float* __restrict__ down_b,
                         const float* __restrict__ up_w) {
    __shared__ float r1[8], r2[8];
    const int t = threadIdx.x, d = blockIdx.x;
    const int log_u = d >> 3, di = d & 7;

    // part 1: down image + c1/c2 partials
    float4 dw = *(const float4*)(down_w + d * HDIM + t * 4);
    float4 nw = *(const float4*)(norm_w + t * 4);
    float4 nb = *(const float4*)(norm_b + t * 4);
    float s1 = 0.f, s2 = 0.f;
    {
        float dwa[4] = {dw.x, dw.y, dw.z, dw.w};
        float nwa[4] = {nw.x, nw.y, nw.z, nw.w};
        float nba[4] = {nb.x, nb.y, nb.z, nb.w};
        #pragma unroll
        for (int j = 0; j < 4; j++) {
            int h = t * 4 + j;
            int k = h & 63, cc = h >> 6;
            __half w2 = __float2half_rn(dwa[j] * nwa[j]);
            g_w2h[cc * 4096 + k * 64 + (log_u ^ (k & 7)) * 8 + di] = w2;
            s1 += __half2float(w2);
            s2 += dwa[j] * nba[j];
        }
    }
    // part 2: up image
    {
        int flat = d * 1024 + t * 4;           // = n*64 + k
        int n = flat >> 6, k0 = flat & 63;
        float4 uv = *(const float4*)(up_w + flat);
        float uva[4] = {uv.x, uv.y, uv.z, uv.w};
        int cc = n >> 6, lu = (n >> 3) & 7, i = n & 7;
        #pragma unroll
        for (int j = 0; j < 4; j++) {
            int k = k0 + j;
            g_uph[cc * 4096 + k * 64 + (lu ^ (k & 7)) * 8 + i] =
                __float2half_rn(uva[j]);
        }
    }
    // reduce c1/c2
    #pragma unroll
    for (int o = 16; o; o >>= 1) {
        s1 += __shfl_xor_sync(0xffffffffu, s1, o);
        s2 += __shfl_xor_sync(0xffffffffu, s2, o);
    }
    if ((t & 31) == 0) { r1[t >> 5] = s1; r2[t >> 5] = s2; }
    __syncthreads();
    if (t == 0) {
        float a1 = 0.f, a2 = 0.f;
        #pragma unroll
        for (int j = 0; j < 8; j++) { a1 += r1[j]; a2 += r2[j]; }
        g_c1[d] = a1;
        g_c2[d] = a2 + down_b[d];
    }
}

// ---------------- fused main kernel ----------------
__global__ void __launch_bounds__(NT, 2)
adapter_main(const float* __restrict__ x,
             const float* __restrict__ up_b,
             float* __restrict__ out) {
    extern __shared__ char smc[];
    const uint32_t sb = smem_u32(smc);
    float* SUB = (float*)(smc + O_SUB);
    float* C1  = (float*)(smc + O_C1);
    float* C2  = (float*)(smc + O_C2);
    float* MU  = (float*)(smc + O_MU);
    float* RS  = (float*)(smc + O_RS);

    const int tid  = threadIdx.x;
    const int lane = tid & 31, w = tid >> 5;
    const int g    = lane >> 2, t4 = lane & 3;
    const int w_m  = w >> 1,   w_n = w & 1;
    const size_t rbase = (size_t)blockIdx.x * TM;

    // loader role
    const int r_l = tid >> 1, hf = tid & 1;
    // ldmatrix address components
    const int laneq = lane & 7;
    const int half8 = (lane >> 3) & 1;
    const int hi16  = lane >> 4;
    int ofsA[2], colA[4], ofsB[2];
    #pragma unroll
    for (int mt = 0; mt < 2; mt++)
        ofsA[mt] = (w_m * 32 + mt * 16 + half8 * 8 + laneq) * 128;
    #pragma unroll
    for (int kt = 0; kt < 4; kt++)
        colA[kt] = ((kt * 2 + hi16) ^ laneq) * 16;
    {
        int kb0 = half8 * 8 + laneq;
        #pragma unroll
        for (int p = 0; p < 2; p++)
            ofsB[p] = kb0 * 128 + ((w_n * 4 + p * 2 + hi16) ^ laneq) * 16;
    }
    // x STS offsets (4 x uint4 per thread)
    int stsOfs[4];
    #pragma unroll
    for (int j = 0; j < 4; j++)
        stsOfs[j] = r_l * 128 + (((hf * 4 + j) ^ (r_l & 7)) * 16);

    for (int i = tid; i < HDIM; i += NT) SUB[i] = up_b[i];
    if (tid < BDIM) { C1[tid] = g_c1[tid]; C2[tid] = g_c2[tid]; }

    float s_acc = 0.f, q_acc = 0.f;

    // ---- prologue: stage chunk 0 (x regs->smem, weights cp.async) ----
    {
        const char* wg = (const char*)g_w2h + tid * 32;
        cpa16(sb + O_W0 + tid * 32, wg);
        cpa16(sb + O_W0 + tid * 32 + 16, wg + 16);
        CPA_COMMIT();

        const float4* xr = (const float4*)(x + (rbase + r_l) * HDIM + hf * 32);
        float4 px[8];
        #pragma unroll
        for (int j = 0; j < 8; j++) px[j] = xr[j];
        #pragma unroll
        for (int j = 0; j < 8; j++) {
            s_acc += (px[j].x + px[j].y) + (px[j].z + px[j].w);
            q_acc += px[j].x * px[j].x + px[j].y * px[j].y
                   + px[j].z * px[j].z + px[j].w * px[j].w;
        }
        #pragma unroll
        for (int j = 0; j < 4; j++) {
            uint4 u = make_uint4(pk2(px[2*j].x, px[2*j].y), pk2(px[2*j].z, px[2*j].w),
                                 pk2(px[2*j+1].x, px[2*j+1].y), pk2(px[2*j+1].z, px[2*j+1].w));
            *(uint4*)(smc + O_XA0 + stsOfs[j]) = u;
        }
        CPA_WAIT0();
    }
    __syncthreads();

    // ---- phase A: down GEMM, K=1024 in 16 chunks of 64 ----
    float acc[2][4][4];
    #pragma unroll
    for (int mt = 0; mt < 2; mt++)
        #pragma unroll
        for (int nt = 0; nt < 4; nt++)
            #pragma unroll
            for (int j = 0; j < 4; j++) acc[mt][nt][j] = 0.f;

    for (int c = 0; c < 16; c++) {
        float4 px[8];
        if (c + 1 < 16) {
            // weights for c+1 via cp.async into the other buffer
            const int wN = (c & 1) ? O_W0 : O_W1;
            const char* wg = (const char*)g_w2h + (c + 1) * 8192 + tid * 32;
            cpa16(sb + wN + tid * 32, wg);
            cpa16(sb + wN + tid * 32 + 16, wg + 16);
            CPA_COMMIT();
            // x for c+1 into registers
            const float4* xr = (const float4*)(x + (rbase + r_l) * HDIM
                                               + (c + 1) * 64 + hf * 32);
            #pragma unroll
            for (int j = 0; j < 8; j++) px[j] = xr[j];
        }
        const uint32_t xaB = sb + ((c & 1) ? O_XA1 : O_XA0);
        const uint32_t wB  = sb + ((c & 1) ? O_W1  : O_W0);
        #pragma unroll
        for (int kt = 0; kt < 4; kt++) {
            uint32_t a[2][4], b[2][4];
            ldm4 (a[0], xaB + ofsA[0] + colA[kt]);
            ldm4 (a[1], xaB + ofsA[1] + colA[kt]);
            ldm4t(b[0], wB + kt * 2048 + ofsB[0]);
            ldm4t(b[1], wB + kt * 2048 + ofsB[1]);
            #pragma unroll
            for (int mt = 0; mt < 2; mt++) {
                mma16(acc[mt][0], a[mt], b[0][0], b[0][1]);
                mma16(acc[mt][1], a[mt], b[0][2], b[0][3]);
                mma16(acc[mt][2], a[mt], b[1][0], b[1][1]);
                mma16(acc[mt][3], a[mt], b[1][2], b[1][3]);
            }
        }
        if (c + 1 < 16) {
            const int xaN = (c & 1) ? O_XA0 : O_XA1;
            #pragma unroll
            for (int j = 0; j < 8; j++) {
                s_acc += (px[j].x + px[j].y) + (px[j].z + px[j].w);
                q_acc += px[j].x * px[j].x + px[j].y * px[j].y
                       + px[j].z * px[j].z + px[j].w * px[j].w;
            }
            #pragma unroll
            for (int j = 0; j < 4; j++) {
                uint4 u = make_uint4(pk2(px[2*j].x, px[2*j].y), pk2(px[2*j].z, px[2*j].w),
                                     pk2(px[2*j+1].x, px[2*j+1].y), pk2(px[2*j+1].z, px[2*j+1].w));
                *(uint4*)(smc + xaN + stsOfs[j]) = u;
            }
            CPA_WAIT0();
        }
        __syncthreads();
    }

    // ---- LN stats: combine the two half-row threads ----
    {
        float s2 = __shfl_xor_sync(0xffffffffu, s_acc, 1);
        float q2 = __shfl_xor_sync(0xffffffffu, q_acc, 1);
        s_acc += s2; q_acc += q2;
        if (hf == 0) {
            float mu  = s_acc * (1.0f / HDIM);
            float var = fmaxf(q_acc * (1.0f / HDIM) - mu * mu, 0.0f);
            MU[r_l] = mu;
            RS[r_l] = rsqrtf(var + 1e-5f);
        }
    }
    __syncthreads();

    // ---- epilogue A: LN fixup + bias + exact GELU -> fp16 h image ----
    #pragma unroll
    for (int mt = 0; mt < 2; mt++) {
        int rA = w_m * 32 + mt * 16 + g, rB = rA + 8;
        float mu1 = MU[rA], rs1 = RS[rA], mu2 = MU[rB], rs2 = RS[rB];
        #pragma unroll
        for (int nt = 0; nt < 4; nt++) {
            int n = w_n * 32 + nt * 8 + 2 * t4;
            float c1a = C1[n], c1b = C1[n + 1];
            float c2a = C2[n], c2b = C2[n + 1];
            float g0 = gelu(rs1 * (acc[mt][nt][0] - mu1 * c1a) + c2a);
            float g1 = gelu(rs1 * (acc[mt][nt][1] - mu1 * c1b) + c2b);
            float g2 = gelu(rs2 * (acc[mt][nt][2] - mu2 * c1a) + c2a);
            float g3 = gelu(rs2 * (acc[mt][nt][3] - mu2 * c1b) + c2b);
            int u = (w_n * 4 + nt);
            *(uint32_t*)(smc + O_H + rA * 128 + ((u ^ g) * 16) + t4 * 4) = pk2(g0, g1);
            *(uint32_t*)(smc + O_H + rB * 128 + ((u ^ g) * 16) + t4 * 4) = pk2(g2, g3);
        }
    }
    // stage up-w chunk 0 while h-image settles
    {
        const char* ug = (const char*)g_uph + tid * 32;
        cpa16(sb + O_W0 + tid * 32, ug);
        cpa16(sb + O_W0 + tid * 32 + 16, ug + 16);
        CPA_COMMIT();
        CPA_WAIT0();
    }
    __syncthreads();

    // ---- phase B prologue: h fragments from smem image ----
    uint32_t ha[4][2][4];
    #pragma unroll
    for (int kt = 0; kt < 4; kt++)
        #pragma unroll
        for (int mt = 0; mt < 2; mt++)
            ldm4(ha[kt][mt], sb + O_H + ofsA[mt] + colA[kt]);

    // ---- phase B: up GEMM (K=64), 16 n-chunks of 64, fused residual ----
    for (int nc = 0; nc < 16; nc++) {
        if (nc + 1 < 16) {
            const int wN = (nc & 1) ? O_W0 : O_W1;
            const char* ug = (const char*)g_uph + (nc + 1) * 8192 + tid * 32;
            cpa16(sb + wN + tid * 32, ug);
            cpa16(sb + wN + tid * 32 + 16, ug + 16);
            CPA_COMMIT();
        }
        // residual prefetch for THIS chunk, hoisted above the MMAs
        float2 rx[2][2][4];
        #pragma unroll
        for (int mt = 0; mt < 2; mt++) {
            int r1 = w_m * 32 + mt * 16 + g;
            const float* xr1 = x + (rbase + r1) * HDIM + nc * 64;
            const float* xr2 = xr1 + 8 * HDIM;
            #pragma unroll
            for (int nt = 0; nt < 4; nt++) {
                int nl = w_n * 32 + nt * 8 + 2 * t4;
                rx[mt][0][nt] = *(const float2*)(xr1 + nl);
                rx[mt][1][nt] = *(const float2*)(xr2 + nl);
            }
        }

        const uint32_t uwB = sb + ((nc & 1) ? O_W1 : O_W0);
        float ub[2][4][4];
        #pragma unroll
        for (int mt = 0; mt < 2; mt++)
            #pragma unroll
            for (int nt = 0; nt < 4; nt++)
                #pragma unroll
                for (int j = 0; j < 4; j++) ub[mt][nt][j] = 0.f;

        #pragma unroll
        for (int kt = 0; kt < 4; kt++) {
            uint32_t b[2][4];
            ldm4t(b[0], uwB + kt * 2048 + ofsB[0]);
            ldm4t(b[1], uwB + kt * 2048 + ofsB[1]);
            #pragma unroll
            for (int mt = 0; mt < 2; mt++) {
                mma16(ub[mt][0], ha[kt][mt], b[0][0], b[0][1]);
                mma16(ub[mt][1], ha[kt][mt], b[0][2], b[0][3]);
                mma16(ub[mt][2], ha[kt][mt], b[1][0], b[1][1]);
                mma16(ub[mt][3], ha[kt][mt], b[1][2], b[1][3]);
            }
        }

        // epilogue: residual + up_b + store
        #pragma unroll
        for (int mt = 0; mt < 2; mt++) {
            int r1 = w_m * 32 + mt * 16 + g;
            float* or1 = out + (rbase + r1) * HDIM + nc * 64;
            float* or2 = or1 + 8 * HDIM;
            #pragma unroll
            for (int nt = 0; nt < 4; nt++) {
                int nl = w_n * 32 + nt * 8 + 2 * t4;
                float b0 = SUB[nc * 64 + nl], b1 = SUB[nc * 64 + nl + 1];
                float2 oa = make_float2(rx[mt][0][nt].x + ub[mt][nt][0] + b0,
                                        rx[mt][0][nt].y + ub[mt][nt][1] + b1);
                float2 ob = make_float2(rx[mt][1][nt].x + ub[mt][nt][2] + b0,
                                        rx[mt][1][nt].y + ub[mt][nt][3] + b1);
                *(float2*)(or1 + nl) = oa;
                *(float2*)(or2 + nl) = ob;
            }
        }
        if (nc + 1 < 16) CPA_WAIT0();
        __syncthreads();
    }
}

// ---------------- launch ----------------
extern "C" void kernel_launch(void* const* d_in, const int* in_sizes, int n_in,
                              void* d_out, int out_size) {
    const float* x      = (const float*)d_in[0];
    const float* norm_w = (const float*)d_in[1];
    const float* norm_b = (const float*)d_in[2];
    const float* down_w = (const float*)d_in[3];
    const float* down_b = (const float*)d_in[4];
    const float* up_w   = (const float*)d_in[5];
    const float* up_b   = (const float*)d_in[6];
    float* out = (float*)d_out;

    int rows = in_sizes[0] / HDIM;

    cudaFuncSetAttribute(adapter_main,
                         cudaFuncAttributeMaxDynamicSharedMemorySize, SMEM_BYTES);

    prep_all<<<BDIM, 256>>>(down_w, norm_w, norm_b, down_b, up_w);
    adapter_main<<<rows / TM, NT, SMEM_BYTES>>>(x, up_b, out);
}

// round 10
// speedup vs baseline: 3.7162x; 1.3470x over previous
#include <cuda_runtime.h>
#include <cuda_fp16.h>
#include <cstdint>

#define HDIM 1024
#define BDIM 64
#define TM   128
#define NT   256

// ---- dynamic smem byte offsets ----
#define O_SUB 0              // up_b, 4KB fp32
#define O_C1  4096           // 256B
#define O_C2  4352
#define O_MU  4608           // 512B fp32 (128 rows)
#define O_RS  5120
#define O_XA0 6144           // 16KB fp16 tile image [128r][64k]
#define O_XA1 22528
#define O_W0  38912          // 8KB fp16 tile image [64k][64n]
#define O_W1  47104
#define SMEM_BYTES 55296
#define O_H   O_XA0          // h image aliases XA0 after phase A
#define O_S   O_XA0          // phase-B fp32 staging tile (32KB = XA0+XA1)

__device__ __half g_w2h[16 * 4096];   // swizzled [kc][k][unit] images, B=[k][d]
__device__ __half g_uph[16 * 4096];   // swizzled [nc][k][unit] images, B=[d][n]
__device__ float  g_c1[BDIM];
__device__ float  g_c2[BDIM];

// ---------------- helpers ----------------
__device__ __forceinline__ uint32_t smem_u32(const void* p) {
    uint32_t a;
    asm("{ .reg .u64 t; cvta.to.shared.u64 t, %1; cvt.u32.u64 %0, t; }"
        : "=r"(a) : "l"(p));
    return a;
}
__device__ __forceinline__ uint32_t pk2(float a, float b) {
    __half2 h = __floats2half2_rn(a, b);
    return *reinterpret_cast<uint32_t*>(&h);
}
__device__ __forceinline__ void cpa16(uint32_t saddr, const void* g) {
    asm volatile("cp.async.cg.shared.global [%0], [%1], 16;"
                 :: "r"(saddr), "l"(g) : "memory");
}
#define CPA_COMMIT() asm volatile("cp.async.commit_group;" ::: "memory")
#define CPA_WAIT0()  asm volatile("cp.async.wait_group 0;" ::: "memory")

__device__ __forceinline__ void ldm4(uint32_t* r, uint32_t addr) {
    asm volatile("ldmatrix.sync.aligned.m8n8.x4.shared.b16 {%0,%1,%2,%3}, [%4];"
                 : "=r"(r[0]), "=r"(r[1]), "=r"(r[2]), "=r"(r[3]) : "r"(addr));
}
__device__ __forceinline__ void ldm4t(uint32_t* r, uint32_t addr) {
    asm volatile("ldmatrix.sync.aligned.m8n8.x4.trans.shared.b16 {%0,%1,%2,%3}, [%4];"
                 : "=r"(r[0]), "=r"(r[1]), "=r"(r[2]), "=r"(r[3]) : "r"(addr));
}
__device__ __forceinline__ void mma16(float* c, const uint32_t* a,
                                      uint32_t b0, uint32_t b1) {
    asm volatile(
        "mma.sync.aligned.m16n8k16.row.col.f32.f16.f16.f32 "
        "{%0,%1,%2,%3}, {%4,%5,%6,%7}, {%8,%9}, {%0,%1,%2,%3};"
        : "+f"(c[0]), "+f"(c[1]), "+f"(c[2]), "+f"(c[3])
        : "r"(a[0]), "r"(a[1]), "r"(a[2]), "r"(a[3]), "r"(b0), "r"(b1));
}
__device__ __forceinline__ float gelu(float v) {
    return 0.5f * v * (1.0f + erff(v * 0.70710678118654752f));
}

// ---------------- merged prep: images + c1/c2, coalesced ----------------
__global__ void prep_all(const float* __restrict__ down_w,
                         const float* __restrict__ norm_w,
                         const float* __restrict__ norm_b,
                         const float* __restrict__ down_b,
                         const float* __restrict__ up_w) {
    __shared__ float r1[8], r2[8];
    const int t = threadIdx.x, d = blockIdx.x;
    const int log_u = d >> 3, di = d & 7;

    float4 dw = *(const float4*)(down_w + d * HDIM + t * 4);
    float4 nw = *(const float4*)(norm_w + t * 4);
    float4 nb = *(const float4*)(norm_b + t * 4);
    float s1 = 0.f, s2 = 0.f;
    {
        float dwa[4] = {dw.x, dw.y, dw.z, dw.w};
        float nwa[4] = {nw.x, nw.y, nw.z, nw.w};
        float nba[4] = {nb.x, nb.y, nb.z, nb.w};
        #pragma unroll
        for (int j = 0; j < 4; j++) {
            int h = t * 4 + j;
            int k = h & 63, cc = h >> 6;
            __half w2 = __float2half_rn(dwa[j] * nwa[j]);
            g_w2h[cc * 4096 + k * 64 + (log_u ^ (k & 7)) * 8 + di] = w2;
            s1 += __half2float(w2);
            s2 += dwa[j] * nba[j];
        }
    }
    {
        int flat = d * 1024 + t * 4;           // = n*64 + k
        int n = flat >> 6, k0 = flat & 63;
        float4 uv = *(const float4*)(up_w + flat);
        float uva[4] = {uv.x, uv.y, uv.z, uv.w};
        int cc = n >> 6, lu = (n >> 3) & 7, i = n & 7;
        #pragma unroll
        for (int j = 0; j < 4; j++) {
            int k = k0 + j;
            g_uph[cc * 4096 + k * 64 + (lu ^ (k & 7)) * 8 + i] =
                __float2half_rn(uva[j]);
        }
    }
    #pragma unroll
    for (int o = 16; o; o >>= 1) {
        s1 += __shfl_xor_sync(0xffffffffu, s1, o);
        s2 += __shfl_xor_sync(0xffffffffu, s2, o);
    }
    if ((t & 31) == 0) { r1[t >> 5] = s1; r2[t >> 5] = s2; }
    __syncthreads();
    if (t == 0) {
        float a1 = 0.f, a2 = 0.f;
        #pragma unroll
        for (int j = 0; j < 8; j++) { a1 += r1[j]; a2 += r2[j]; }
        g_c1[d] = a1;
        g_c2[d] = a2 + down_b[d];
    }
}

// ---------------- fused main kernel ----------------
__global__ void __launch_bounds__(NT, 2)
adapter_main(const float* __restrict__ x,
             const float* __restrict__ up_b,
             float* __restrict__ out) {
    extern __shared__ char smc[];
    const uint32_t sb = smem_u32(smc);
    float* SUB = (float*)(smc + O_SUB);
    float* C1  = (float*)(smc + O_C1);
    float* C2  = (float*)(smc + O_C2);
    float* MU  = (float*)(smc + O_MU);
    float* RS  = (float*)(smc + O_RS);

    const int tid  = threadIdx.x;
    const int lane = tid & 31, w = tid >> 5;
    const int g    = lane >> 2, t4 = lane & 3;
    const int w_m  = w >> 1,   w_n = w & 1;
    const size_t rbase = (size_t)blockIdx.x * TM;

    // phase-A loader role: 4 lanes per row, rows rq and rq+64
    const int rq = tid >> 2, q = tid & 3;
    const int qh = q >> 1, ql = q & 1;
    // x-image STS offsets (row rq; row rq+64 = +8192)
    int stsA[4];
    #pragma unroll
    for (int j = 0; j < 4; j++) {
        int u = j * 2 + qh;
        stsA[j] = rq * 128 + (((u ^ (rq & 7)) & 15) << 4) + ql * 8;
    }
    // ldmatrix address components (image layout unchanged)
    const int laneq = lane & 7;
    const int half8 = (lane >> 3) & 1;
    const int hi16  = lane >> 4;
    int ofsA[2], colA[4], ofsB[2];
    #pragma unroll
    for (int mt = 0; mt < 2; mt++)
        ofsA[mt] = (w_m * 32 + mt * 16 + half8 * 8 + laneq) * 128;
    #pragma unroll
    for (int kt = 0; kt < 4; kt++)
        colA[kt] = ((kt * 2 + hi16) ^ laneq) * 16;
    {
        int kb0 = half8 * 8 + laneq;
        #pragma unroll
        for (int p = 0; p < 2; p++)
            ofsB[p] = kb0 * 128 + ((w_n * 4 + p * 2 + hi16) ^ laneq) * 16;
    }
    // phase-B staging STS offsets [mt][nt] (row rA; rB = +2048)
    int stg[2][4];
    #pragma unroll
    for (int mt = 0; mt < 2; mt++)
        #pragma unroll
        for (int nt = 0; nt < 4; nt++) {
            int u = w_n * 8 + nt * 2 + (t4 >> 1);
            int r = w_m * 32 + mt * 16 + g;
            stg[mt][nt] = r * 256 + (((u ^ (g << 1)) & 15) << 4) + (t4 & 1) * 8;
        }
    // phase-B output pass constants
    const int po_u  = tid & 15;                 // unit within row
    const int po_r0 = tid >> 4;                 // base row (p adds 16)
    const int po_sw = (((po_u ^ ((po_r0 & 7) << 1)) & 15) << 4);

    for (int i = tid; i < HDIM; i += NT) SUB[i] = up_b[i];
    if (tid < BDIM) { C1[tid] = g_c1[tid]; C2[tid] = g_c2[tid]; }

    float s0 = 0.f, q0 = 0.f, s1 = 0.f, q1 = 0.f;

    // ---- prologue: stage chunk 0 (x regs->smem, weights cp.async) ----
    {
        const char* wg = (const char*)g_w2h + tid * 32;
        cpa16(sb + O_W0 + tid * 32, wg);
        cpa16(sb + O_W0 + tid * 32 + 16, wg + 16);
        CPA_COMMIT();

        const float* xr0 = x + (rbase + rq) * HDIM;
        const float* xr1 = xr0 + 64 * HDIM;
        float4 px[8];
        #pragma unroll
        for (int j = 0; j < 4; j++) px[j]     = *(const float4*)(xr0 + q * 4 + j * 16);
        #pragma unroll
        for (int j = 0; j < 4; j++) px[4 + j] = *(const float4*)(xr1 + q * 4 + j * 16);
        #pragma unroll
        for (int j = 0; j < 4; j++) {
            s0 += (px[j].x + px[j].y) + (px[j].z + px[j].w);
            q0 += px[j].x * px[j].x + px[j].y * px[j].y
                + px[j].z * px[j].z + px[j].w * px[j].w;
            s1 += (px[4+j].x + px[4+j].y) + (px[4+j].z + px[4+j].w);
            q1 += px[4+j].x * px[4+j].x + px[4+j].y * px[4+j].y
                + px[4+j].z * px[4+j].z + px[4+j].w * px[4+j].w;
        }
        #pragma unroll
        for (int j = 0; j < 4; j++) {
            *(uint2*)(smc + O_XA0 + stsA[j]) =
                make_uint2(pk2(px[j].x, px[j].y), pk2(px[j].z, px[j].w));
            *(uint2*)(smc + O_XA0 + stsA[j] + 8192) =
                make_uint2(pk2(px[4+j].x, px[4+j].y), pk2(px[4+j].z, px[4+j].w));
        }
        CPA_WAIT0();
    }
    __syncthreads();

    // ---- phase A: down GEMM, K=1024 in 16 chunks of 64 ----
    float acc[2][4][4];
    #pragma unroll
    for (int mt = 0; mt < 2; mt++)
        #pragma unroll
        for (int nt = 0; nt < 4; nt++)
            #pragma unroll
            for (int j = 0; j < 4; j++) acc[mt][nt][j] = 0.f;

    for (int c = 0; c < 16; c++) {
        float4 px[8];
        if (c + 1 < 16) {
            const int wN = (c & 1) ? O_W0 : O_W1;
            const char* wg = (const char*)g_w2h + (c + 1) * 8192 + tid * 32;
            cpa16(sb + wN + tid * 32, wg);
            cpa16(sb + wN + tid * 32 + 16, wg + 16);
            CPA_COMMIT();
            const float* xr0 = x + (rbase + rq) * HDIM + (c + 1) * 64;
            const float* xr1 = xr0 + 64 * HDIM;
            #pragma unroll
            for (int j = 0; j < 4; j++) px[j]     = *(const float4*)(xr0 + q * 4 + j * 16);
            #pragma unroll
            for (int j = 0; j < 4; j++) px[4 + j] = *(const float4*)(xr1 + q * 4 + j * 16);
        }
        const uint32_t xaB = sb + ((c & 1) ? O_XA1 : O_XA0);
        const uint32_t wB  = sb + ((c & 1) ? O_W1  : O_W0);
        #pragma unroll
        for (int kt = 0; kt < 4; kt++) {
            uint32_t a[2][4], b[2][4];
            ldm4 (a[0], xaB + ofsA[0] + colA[kt]);
            ldm4 (a[1], xaB + ofsA[1] + colA[kt]);
            ldm4t(b[0], wB + kt * 2048 + ofsB[0]);
            ldm4t(b[1], wB + kt * 2048 + ofsB[1]);
            #pragma unroll
            for (int mt = 0; mt < 2; mt++) {
                mma16(acc[mt][0], a[mt], b[0][0], b[0][1]);
                mma16(acc[mt][1], a[mt], b[0][2], b[0][3]);
                mma16(acc[mt][2], a[mt], b[1][0], b[1][1]);
                mma16(acc[mt][3], a[mt], b[1][2], b[1][3]);
            }
        }
        if (c + 1 < 16) {
            const int xaN = (c & 1) ? O_XA0 : O_XA1;
            #pragma unroll
            for (int j = 0; j < 4; j++) {
                s0 += (px[j].x + px[j].y) + (px[j].z + px[j].w);
                q0 += px[j].x * px[j].x + px[j].y * px[j].y
                    + px[j].z * px[j].z + px[j].w * px[j].w;
                s1 += (px[4+j].x + px[4+j].y) + (px[4+j].z + px[4+j].w);
                q1 += px[4+j].x * px[4+j].x + px[4+j].y * px[4+j].y
                    + px[4+j].z * px[4+j].z + px[4+j].w * px[4+j].w;
            }
            #pragma unroll
            for (int j = 0; j < 4; j++) {
                *(uint2*)(smc + xaN + stsA[j]) =
                    make_uint2(pk2(px[j].x, px[j].y), pk2(px[j].z, px[j].w));
                *(uint2*)(smc + xaN + stsA[j] + 8192) =
                    make_uint2(pk2(px[4+j].x, px[4+j].y), pk2(px[4+j].z, px[4+j].w));
            }
            CPA_WAIT0();
        }
        __syncthreads();
    }

    // ---- LN stats: reduce over the 4 q-lanes ----
    {
        s0 += __shfl_xor_sync(0xffffffffu, s0, 1);
        s0 += __shfl_xor_sync(0xffffffffu, s0, 2);
        q0 += __shfl_xor_sync(0xffffffffu, q0, 1);
        q0 += __shfl_xor_sync(0xffffffffu, q0, 2);
        s1 += __shfl_xor_sync(0xffffffffu, s1, 1);
        s1 += __shfl_xor_sync(0xffffffffu, s1, 2);
        q1 += __shfl_xor_sync(0xffffffffu, q1, 1);
        q1 += __shfl_xor_sync(0xffffffffu, q1, 2);
        if (q == 0) {
            float mu  = s0 * (1.0f / HDIM);
            float var = fmaxf(q0 * (1.0f / HDIM) - mu * mu, 0.0f);
            MU[rq] = mu;
            RS[rq] = rsqrtf(var + 1e-5f);
            mu  = s1 * (1.0f / HDIM);
            var = fmaxf(q1 * (1.0f / HDIM) - mu * mu, 0.0f);
            MU[rq + 64] = mu;
            RS[rq + 64] = rsqrtf(var + 1e-5f);
        }
    }
    __syncthreads();

    // ---- epilogue A: LN fixup + bias + exact GELU -> fp16 h image ----
    #pragma unroll
    for (int mt = 0; mt < 2; mt++) {
        int rA = w_m * 32 + mt * 16 + g, rB = rA + 8;
        float mu1 = MU[rA], rs1 = RS[rA], mu2 = MU[rB], rs2 = RS[rB];
        #pragma unroll
        for (int nt = 0; nt < 4; nt++) {
            int n = w_n * 32 + nt * 8 + 2 * t4;
            float c1a = C1[n], c1b = C1[n + 1];
            float c2a = C2[n], c2b = C2[n + 1];
            float g0 = gelu(rs1 * (acc[mt][nt][0] - mu1 * c1a) + c2a);
            float g1 = gelu(rs1 * (acc[mt][nt][1] - mu1 * c1b) + c2b);
            float g2 = gelu(rs2 * (acc[mt][nt][2] - mu2 * c1a) + c2a);
            float g3 = gelu(rs2 * (acc[mt][nt][3] - mu2 * c1b) + c2b);
            int u = (w_n * 4 + nt);
            *(uint32_t*)(smc + O_H + rA * 128 + ((u ^ g) * 16) + t4 * 4) = pk2(g0, g1);
            *(uint32_t*)(smc + O_H + rB * 128 + ((u ^ g) * 16) + t4 * 4) = pk2(g2, g3);
        }
    }
    // stage up-w chunk 0 while h-image settles
    {
        const char* ug = (const char*)g_uph + tid * 32;
        cpa16(sb + O_W0 + tid * 32, ug);
        cpa16(sb + O_W0 + tid * 32 + 16, ug + 16);
        CPA_COMMIT();
        CPA_WAIT0();
    }
    __syncthreads();

    // ---- phase B prologue: h fragments from smem image ----
    uint32_t ha[4][2][4];
    #pragma unroll
    for (int kt = 0; kt < 4; kt++)
        #pragma unroll
        for (int mt = 0; mt < 2; mt++)
            ldm4(ha[kt][mt], sb + O_H + ofsA[mt] + colA[kt]);
    __syncthreads();   // staging below overwrites the h image — all ha loads must land

    // ---- phase B: up GEMM (K=64), 16 n-chunks of 64 ----
    for (int nc = 0; nc < 16; nc++) {
        if (nc + 1 < 16) {
            const int wN = (nc & 1) ? O_W0 : O_W1;
            const char* ug = (const char*)g_uph + (nc + 1) * 8192 + tid * 32;
            cpa16(sb + wN + tid * 32, ug);
            cpa16(sb + wN + tid * 32 + 16, ug + 16);
            CPA_COMMIT();
        }
        const uint32_t uwB = sb + ((nc & 1) ? O_W1 : O_W0);
        float ub[2][4][4];
        #pragma unroll
        for (int mt = 0; mt < 2; mt++)
            #pragma unroll
            for (int nt = 0; nt < 4; nt++)
                #pragma unroll
                for (int j = 0; j < 4; j++) ub[mt][nt][j] = 0.f;

        #pragma unroll
        for (int kt = 0; kt < 4; kt++) {
            uint32_t b[2][4];
            ldm4t(b[0], uwB + kt * 2048 + ofsB[0]);
            ldm4t(b[1], uwB + kt * 2048 + ofsB[1]);
            #pragma unroll
            for (int mt = 0; mt < 2; mt++) {
                mma16(ub[mt][0], ha[kt][mt], b[0][0], b[0][1]);
                mma16(ub[mt][1], ha[kt][mt], b[0][2], b[0][3]);
                mma16(ub[mt][2], ha[kt][mt], b[1][0], b[1][1]);
                mma16(ub[mt][3], ha[kt][mt], b[1][2], b[1][3]);
            }
        }

        // stage fragments -> fp32 tile (swizzled)
        #pragma unroll
        for (int mt = 0; mt < 2; mt++)
            #pragma unroll
            for (int nt = 0; nt < 4; nt++) {
                *(float2*)(smc + O_S + stg[mt][nt]) =
                    make_float2(ub[mt][nt][0], ub[mt][nt][1]);
                *(float2*)(smc + O_S + stg[mt][nt] + 2048) =
                    make_float2(ub[mt][nt][2], ub[mt][nt][3]);
            }
        __syncthreads();

        // coalesced output pass: residual + bias + store
        {
            float4 bb = *(const float4*)(SUB + nc * 64 + po_u * 4);
            #pragma unroll
            for (int p = 0; p < 8; p++) {
                int r = po_r0 + p * 16;
                float4 v  = *(const float4*)(smc + O_S + r * 256 + po_sw);
                const size_t go = (rbase + r) * HDIM + nc * 64 + po_u * 4;
                float4 xv = *(const float4*)(x + go);
                float4 o;
                o.x = xv.x + v.x + bb.x;
                o.y = xv.y + v.y + bb.y;
                o.z = xv.z + v.z + bb.z;
                o.w = xv.w + v.w + bb.w;
                *(float4*)(out + go) = o;
            }
        }
        if (nc + 1 < 16) CPA_WAIT0();
        __syncthreads();
    }
}

// ---------------- launch ----------------
extern "C" void kernel_launch(void* const* d_in, const int* in_sizes, int n_in,
                              void* d_out, int out_size) {
    const float* x      = (const float*)d_in[0];
    const float* norm_w = (const float*)d_in[1];
    const float* norm_b = (const float*)d_in[2];
    const float* down_w = (const float*)d_in[3];
    const float* down_b = (const float*)d_in[4];
    const float* up_w   = (const float*)d_in[5];
    const float* up_b   = (const float*)d_in[6];
    float* out = (float*)d_out;

    int rows = in_sizes[0] / HDIM;

    cudaFuncSetAttribute(adapter_main,
                         cudaFuncAttributeMaxDynamicSharedMemorySize, SMEM_BYTES);

    prep_all<<<BDIM, 256>>>(down_w, norm_w, norm_b, down_b, up_w);
    adapter_main<<<rows / TM, NT, SMEM_BYTES>>>(x, up_b, out);
}